// round 9
// baseline (speedup 1.0000x reference)
#include <cuda_runtime.h>
#include <cstdint>

// LogicLayer: out[i,j] = g_a(x[i,idx_a[j]]) * g_b(x[i,idx_b[j]])
//   g(v) = (logit > 0) ? 1-v : v
//
// R9 vs R8 (60.1us = 53.8 main + ~6 prep/launch):
//  - 13-slot x 16KB smem chunk ring (208KB): row n lives in slots
//    (8n+c) mod 13. 5 spare slots take next row's first 5 chunk fills
//    DURING the gather phase; last 3 fill right after the sync.
//    Fill exposure ~3100 -> ~1200 cyc/row (was fully serialized).
//  - gather address adds slot arithmetic (+3 ALU/gather; issue had headroom)

#define IN_DIM   32768
#define OUT_DIM  32768
#define BATCH    1024
#define NTHREADS 1024
#define NSM      148
#define ITERS2   (OUT_DIM / (NTHREADS * 2))   // 16
#define NSLOTS   13
#define CHUNK_FLOATS 4096
#define CHUNK_BYTES  16384
#define ROW_CHUNKS   8
#define EARLY_CHUNKS 5                         // fills overlapped with gather

__device__ uint32_t g_packed[OUT_DIM];

// ---------------- prep: pack (fa|ia | fb|ib) into one u32 per j --------------
__global__ __launch_bounds__(256)
void prep_kernel(const float* __restrict__ logits,
                 const int* __restrict__ idx_a,
                 const int* __restrict__ idx_b) {
    int j = blockIdx.x * 256 + threadIdx.x;
    uint32_t ia = (uint32_t)idx_a[j] & 0x7FFFu;
    uint32_t ib = (uint32_t)idx_b[j] & 0x7FFFu;
    uint32_t fa = (logits[2 * j]     > 0.0f) ? 1u : 0u;
    uint32_t fb = (logits[2 * j + 1] > 0.0f) ? 1u : 0u;
    g_packed[j] = (fa << 31) | (ia << 16) | (fb << 15) | ib;
}

// ---------------- main: persistent, chunk-ring TMA pipeline ------------------
__device__ __forceinline__ uint32_t smem_u32(const void* p) {
    uint32_t a;
    asm("{ .reg .u64 t; cvta.to.shared.u64 t, %1; cvt.u32.u64 %0, t; }"
        : "=r"(a) : "l"(p));
    return a;
}

__device__ __forceinline__ void stg_cs_v2(float* p, float v0, float v1) {
    asm volatile("st.global.cs.v2.f32 [%0], {%1, %2};"
                 :: "l"(p), "f"(v0), "f"(v1) : "memory");
}

__device__ __forceinline__ void mbar_wait(uint32_t mbar_a, uint32_t phase) {
    uint32_t done;
    asm volatile(
        "{\n\t.reg .pred P;\n\t"
        "mbarrier.try_wait.parity.acquire.cta.shared::cta.b64 P, [%1], %2, 0x989680;\n\t"
        "selp.b32 %0, 1, 0, P;\n\t}"
        : "=r"(done) : "r"(mbar_a), "r"(phase) : "memory");
    if (!done) {
        asm volatile(
            "{\n\t.reg .pred P;\n"
            "WL_%=:\n\t"
            "mbarrier.try_wait.parity.acquire.cta.shared::cta.b64 P, [%0], %1, 0x989680;\n\t"
            "@P bra.uni WD_%=;\n\t"
            "bra.uni WL_%=;\n"
            "WD_%=:\n\t}"
            :: "r"(mbar_a), "r"(phase) : "memory");
    }
}

__device__ __forceinline__ void tma_chunk(uint32_t dst_a, const float* src,
                                          uint32_t mbar_a) {
    asm volatile("cp.async.bulk.shared::cta.global.mbarrier::complete_tx::bytes "
                 "[%0], [%1], %2, [%3];"
                 :: "r"(dst_a), "l"(src), "r"((uint32_t)CHUNK_BYTES), "r"(mbar_a)
                 : "memory");
}

// gather index -> smem float index given row's start slot s
__device__ __forceinline__ float gat(const float* sx, uint32_t s, uint32_t i) {
    uint32_t slot = s + (i >> 12);
    slot = min(slot, slot - (uint32_t)NSLOTS);   // unsigned wrap => mod 13
    return sx[(slot << 12) | (i & 4095u)];
}

__global__ __launch_bounds__(NTHREADS, 1)
void logic_layer_kernel(const float* __restrict__ x,
                        float* __restrict__ out) {
    extern __shared__ float sx[];
    __shared__ __align__(8) uint64_t mbar;

    const int t = threadIdx.x;
    const uint32_t mbar_a = smem_u32(&mbar);
    const uint32_t base_a = smem_u32(sx);
    const uint2* packed2 = reinterpret_cast<const uint2*>(g_packed);

    if (t == 0) {
        asm volatile("mbarrier.init.shared.b64 [%0], 1;" :: "r"(mbar_a) : "memory");
        asm volatile("fence.proxy.async.shared::cta;" ::: "memory");
    }
    __syncthreads();

    // First row: fill all 8 chunks into slots 0..7.
    if (t == 0) {
        asm volatile("mbarrier.arrive.expect_tx.shared.b64 _, [%0], %1;"
                     :: "r"(mbar_a), "r"((uint32_t)(ROW_CHUNKS * CHUNK_BYTES)) : "memory");
        const float* xr = x + (size_t)blockIdx.x * IN_DIM;
        #pragma unroll
        for (int c = 0; c < ROW_CHUNKS; c++)
            tma_chunk(base_a + c * CHUNK_BYTES, xr + c * CHUNK_FLOATS, mbar_a);
    }

    uint32_t phase = 0;
    uint32_t s = 0;                    // start slot of current row

    for (int row = blockIdx.x; row < BATCH; row += NSM) {
        const int nrow = row + NSM;
        const uint32_t ns = (s + ROW_CHUNKS) % NSLOTS;  // next row's start slot

        // Pull this CTA's next row toward L2.
        if (t == 32 && nrow < BATCH) {
            asm volatile("cp.async.bulk.prefetch.L2.global [%0], %1;"
                         :: "l"(x + (size_t)nrow * IN_DIM),
                            "r"((uint32_t)(IN_DIM * 4)) : "memory");
        }

        // Prime packed ring (gmem only) while fill streams in.
        uint2 pr[4];
        #pragma unroll
        for (int k = 0; k < 4; k++) pr[k] = packed2[k * NTHREADS + t];

        mbar_wait(mbar_a, phase);
        phase ^= 1;

        // Early fills: next row's chunks 0..4 into the 5 spare slots.
        if (t == 0 && nrow < BATCH) {
            asm volatile("mbarrier.arrive.expect_tx.shared.b64 _, [%0], %1;"
                         :: "r"(mbar_a), "r"((uint32_t)(ROW_CHUNKS * CHUNK_BYTES)) : "memory");
            const float* xr = x + (size_t)nrow * IN_DIM;
            #pragma unroll
            for (int c = 0; c < EARLY_CHUNKS; c++) {
                uint32_t slot = ns + c; if (slot >= NSLOTS) slot -= NSLOTS;
                tma_chunk(base_a + slot * CHUNK_BYTES, xr + c * CHUNK_FLOATS, mbar_a);
            }
        }

        float* orow = out + (size_t)row * OUT_DIM;

        #pragma unroll
        for (int k = 0; k < ITERS2; k++) {
            uint2 p = pr[k & 3];
            if (k + 4 < ITERS2) pr[k & 3] = packed2[(k + 4) * NTHREADS + t];
            float a0 = gat(sx, s, (p.x >> 16) & 0x7FFFu);
            float b0 = gat(sx, s, p.x & 0x7FFFu);
            float a1 = gat(sx, s, (p.y >> 16) & 0x7FFFu);
            float b1 = gat(sx, s, p.y & 0x7FFFu);
            if (p.x & 0x80000000u) a0 = 1.0f - a0;
            if (p.x & 0x00008000u) b0 = 1.0f - b0;
            if (p.y & 0x80000000u) a1 = 1.0f - a1;
            if (p.y & 0x00008000u) b1 = 1.0f - b1;
            stg_cs_v2(&orow[(size_t)k * NTHREADS * 2 + t * 2], a0 * b0, a1 * b1);
        }

        __syncthreads();  // row's slots now free

        // Late fills: next row's chunks 5..7 into just-freed slots.
        if (t == 0 && nrow < BATCH) {
            const float* xr = x + (size_t)nrow * IN_DIM;
            #pragma unroll
            for (int c = EARLY_CHUNKS; c < ROW_CHUNKS; c++) {
                uint32_t slot = ns + c; if (slot >= NSLOTS) slot -= NSLOTS;
                tma_chunk(base_a + slot * CHUNK_BYTES, xr + c * CHUNK_FLOATS, mbar_a);
            }
        }
        s = ns;
    }
}

extern "C" void kernel_launch(void* const* d_in, const int* in_sizes, int n_in,
                              void* d_out, int out_size) {
    const float* x      = (const float*)d_in[0];
    const float* logits = (const float*)d_in[1];
    const int*   idx_a  = (const int*)d_in[2];
    const int*   idx_b  = (const int*)d_in[3];
    float* out = (float*)d_out;

    cudaFuncSetAttribute(logic_layer_kernel,
                         cudaFuncAttributeMaxDynamicSharedMemorySize,
                         NSLOTS * CHUNK_BYTES);

    prep_kernel<<<OUT_DIM / 256, 256>>>(logits, idx_a, idx_b);
    logic_layer_kernel<<<NSM, NTHREADS, NSLOTS * CHUNK_BYTES>>>(x, out);
}